// round 7
// baseline (speedup 1.0000x reference)
#include <cuda_runtime.h>
#include <cstdint>

#define NN 50000
#define NE 800000
#define NGR 512
#define BN_EPS 1e-5f

// ---------------- scratch (static __device__ — no allocations) ----------------
__device__ float4 g_agg[NN * 16];
__device__ float4 g_z2 [NN * 16];
__device__ float  g_stats[384];          // 3 layers x (sum[64], sumsq[64])
__device__ float4 g_pool[NGR * 16];
__device__ float  g_mid [NGR * 128];
__device__ int    g_deg[NN];
__device__ int    g_rowptr[NN + 1];
__device__ int    g_cursor[NN];
__device__ int    g_csr[NE];

// packed fp32x2 FMA (Blackwell family-level instruction, not an 'a' feature)
__device__ __forceinline__ void fma2(unsigned long long& acc,
                                     unsigned long long a,
                                     unsigned long long b) {
    asm("fma.rn.f32x2 %0, %1, %2, %0;" : "+l"(acc) : "l"(a), "l"(b));
}
__device__ __forceinline__ float fma2_reduce(unsigned long long acc) {
    float lo = __uint_as_float((uint32_t)acc);
    float hi = __uint_as_float((uint32_t)(acc >> 32));
    return lo + hi;
}
__device__ __forceinline__ void f4add(float4& a, float4 b) {
    a.x += b.x; a.y += b.y; a.z += b.z; a.w += b.w;
}

// ---------------- CSR build ----------------

__global__ void k_init(int* __restrict__ deg, float* __restrict__ stats,
                       float* __restrict__ pool) {
    int i = blockIdx.x * blockDim.x + threadIdx.x;
    if (i < NN) deg[i] = 0;
    if (i < 384) stats[i] = 0.0f;
    if (i < NGR * 64) pool[i] = 0.0f;
}

__global__ void k_hist(const int* __restrict__ ei, int* __restrict__ deg) {
    int e = blockIdx.x * blockDim.x + threadIdx.x;
    if (e < NE) atomicAdd(&deg[ei[NE + e]], 1);
}

__global__ void k_scan(const int* __restrict__ deg, int* __restrict__ rowptr,
                       int* __restrict__ cursor) {
    __shared__ int part[1024];
    const int t = threadIdx.x;
    const int CH = (NN + 1023) / 1024;             // 49
    int start = t * CH;
    int end = start + CH; if (end > NN) end = NN;
    int s = 0;
    for (int i = start; i < end; i++) s += deg[i];
    part[t] = s;
    __syncthreads();
    for (int off = 1; off < 1024; off <<= 1) {
        int v = part[t];
        int add = (t >= off) ? part[t - off] : 0;
        __syncthreads();
        part[t] = v + add;
        __syncthreads();
    }
    int run = (t > 0) ? part[t - 1] : 0;
    for (int i = start; i < end; i++) {
        rowptr[i] = run;
        cursor[i] = run;
        run += deg[i];
    }
    if (t == 1023) rowptr[NN] = run;
}

__global__ void k_fill(const int* __restrict__ ei, int* __restrict__ cursor,
                       int* __restrict__ csr) {
    int e = blockIdx.x * blockDim.x + threadIdx.x;
    if (e >= NE) return;
    int pos = atomicAdd(&cursor[ei[NE + e]], 1);
    csr[pos] = ei[e];
}

// pull-gather with optional fused BN of the PREVIOUS layer (exact algebraic form):
//   out[n] = sc * (z[n] + sum_{s in N(n)} z[s]) + (deg(n)+1) * sh
// stats==null -> identity (layer 1, raw x input). 4-way ILP on the neighbor loop.
__global__ void k_gather_bn(const float4* __restrict__ h,
                            const int* __restrict__ rowptr,
                            const int* __restrict__ csr,
                            const float* __restrict__ stats,
                            const float* __restrict__ gamma,
                            const float* __restrict__ beta,
                            float4* __restrict__ out) {
    __shared__ float sc[64], sh[64];
    const int t = threadIdx.x;
    if (stats != nullptr) {
        if (t < 64) {
            float mean = stats[t] * (1.0f / NN);
            float var  = stats[64 + t] * (1.0f / NN) - mean * mean;
            float s = gamma[t] * rsqrtf(var + BN_EPS);
            sc[t] = s;
            sh[t] = beta[t] - mean * s;
        }
        __syncthreads();
    }
    int i = blockIdx.x * blockDim.x + t;
    if (i >= NN * 16) return;
    int n = i >> 4;
    int j = i & 15;
    int b = rowptr[n], e = rowptr[n + 1];

    float4 a0 = h[n * 16 + j];                      // self term
    float4 a1 = make_float4(0.f, 0.f, 0.f, 0.f);
    float4 a2 = make_float4(0.f, 0.f, 0.f, 0.f);
    float4 a3 = make_float4(0.f, 0.f, 0.f, 0.f);

    int idx = b;
    for (; idx + 4 <= e; idx += 4) {
        int s0 = __ldg(&csr[idx + 0]);
        int s1 = __ldg(&csr[idx + 1]);
        int s2 = __ldg(&csr[idx + 2]);
        int s3 = __ldg(&csr[idx + 3]);
        float4 v0 = h[s0 * 16 + j];
        float4 v1 = h[s1 * 16 + j];
        float4 v2 = h[s2 * 16 + j];
        float4 v3 = h[s3 * 16 + j];
        f4add(a0, v0); f4add(a1, v1); f4add(a2, v2); f4add(a3, v3);
    }
    for (; idx < e; idx++) {
        float4 v = h[__ldg(&csr[idx]) * 16 + j];
        f4add(a0, v);
    }
    f4add(a0, a1); f4add(a2, a3); f4add(a0, a2);

    if (stats != nullptr) {
        float cnt = (float)(e - b + 1);
        int c = j * 4;
        a0.x = a0.x * sc[c + 0] + cnt * sh[c + 0];
        a0.y = a0.y * sc[c + 1] + cnt * sh[c + 1];
        a0.z = a0.z * sc[c + 2] + cnt * sh[c + 2];
        a0.w = a0.w * sc[c + 3] + cnt * sh[c + 3];
    }
    out[i] = a0;
}

// ---------------- fused MLP (unchanged) ----------------
__global__ void __launch_bounds__(256) k_gin_mlp(
        const float* __restrict__ A,
        const float* __restrict__ Wa, const float* __restrict__ ba,
        const float* __restrict__ Wb, const float* __restrict__ bb,
        float* __restrict__ Z2, float* __restrict__ stats, int rows) {
    __shared__ float As[128][68];
    __shared__ float4 Wc[16][64];
    __shared__ float s_sum[64], s_sq[64], sbias_a[64], sbias_b[64];

    const int t = threadIdx.x;
    const int tx = t & 15;
    const int ty = t >> 4;
    const int rb = ty * 8;
    const int row0 = blockIdx.x * 128;

    for (int i = t; i < 1024; i += 256) {
        int kk = i >> 6, c = i & 63;
        Wc[kk][c] = make_float4(Wa[(4 * kk + 0) * 64 + c], Wa[(4 * kk + 1) * 64 + c],
                                Wa[(4 * kk + 2) * 64 + c], Wa[(4 * kk + 3) * 64 + c]);
    }
    for (int i = t; i < 2048; i += 256) {
        int r = i >> 4, kc = i & 15;
        float4 v = make_float4(0.f, 0.f, 0.f, 0.f);
        if (row0 + r < rows) v = ((const float4*)A)[(row0 + r) * 16 + kc];
        *(float4*)&As[r][kc * 4] = v;
    }
    if (t < 64) { s_sum[t] = 0.f; s_sq[t] = 0.f; sbias_a[t] = ba[t]; sbias_b[t] = bb[t]; }
    __syncthreads();

    unsigned long long acc[8][4];
#pragma unroll
    for (int i = 0; i < 8; i++)
#pragma unroll
        for (int j = 0; j < 4; j++) acc[i][j] = 0ull;

#pragma unroll 4
    for (int kk = 0; kk < 16; kk++) {
        ulonglong2 w[4];
#pragma unroll
        for (int j = 0; j < 4; j++)
            w[j] = *(const ulonglong2*)&Wc[kk][tx + 16 * j];
#pragma unroll
        for (int i = 0; i < 8; i++) {
            ulonglong2 a = *(const ulonglong2*)&As[rb + i][kk * 4];
#pragma unroll
            for (int j = 0; j < 4; j++) {
                fma2(acc[i][j], a.x, w[j].x);
                fma2(acc[i][j], a.y, w[j].y);
            }
        }
    }
    __syncthreads();

#pragma unroll
    for (int i = 0; i < 8; i++) {
#pragma unroll
        for (int j = 0; j < 4; j++) {
            int c = tx + 16 * j;
            float v = fmaxf(fma2_reduce(acc[i][j]) + sbias_a[c], 0.f);
            As[rb + i][c] = v;
            acc[i][j] = 0ull;
        }
    }
    for (int i = t; i < 1024; i += 256) {
        int kk = i >> 6, c = i & 63;
        Wc[kk][c] = make_float4(Wb[(4 * kk + 0) * 64 + c], Wb[(4 * kk + 1) * 64 + c],
                                Wb[(4 * kk + 2) * 64 + c], Wb[(4 * kk + 3) * 64 + c]);
    }
    __syncthreads();

#pragma unroll 4
    for (int kk = 0; kk < 16; kk++) {
        ulonglong2 w[4];
#pragma unroll
        for (int j = 0; j < 4; j++)
            w[j] = *(const ulonglong2*)&Wc[kk][tx + 16 * j];
#pragma unroll
        for (int i = 0; i < 8; i++) {
            ulonglong2 a = *(const ulonglong2*)&As[rb + i][kk * 4];
#pragma unroll
            for (int j = 0; j < 4; j++) {
                fma2(acc[i][j], a.x, w[j].x);
                fma2(acc[i][j], a.y, w[j].y);
            }
        }
    }

    float s[4] = {0.f, 0.f, 0.f, 0.f};
    float q[4] = {0.f, 0.f, 0.f, 0.f};
#pragma unroll
    for (int i = 0; i < 8; i++) {
        int r = row0 + rb + i;
        if (r < rows) {
#pragma unroll
            for (int j = 0; j < 4; j++) {
                int c = tx + 16 * j;
                float v = fmaxf(fma2_reduce(acc[i][j]) + sbias_b[c], 0.f);
                Z2[r * 64 + c] = v;
                s[j] += v;
                q[j] += v * v;
            }
        }
    }
#pragma unroll
    for (int j = 0; j < 4; j++) {
        s[j] += __shfl_down_sync(0xffffffff, s[j], 16);
        q[j] += __shfl_down_sync(0xffffffff, q[j], 16);
    }
    if ((t & 31) < 16) {
#pragma unroll
        for (int j = 0; j < 4; j++) {
            atomicAdd(&s_sum[tx + 16 * j], s[j]);
            atomicAdd(&s_sq[tx + 16 * j], q[j]);
        }
    }
    __syncthreads();
    if (t < 64) {
        atomicAdd(&stats[t], s_sum[t]);
        atomicAdd(&stats[64 + t], s_sq[t]);
    }
}

// ---------------- layer-3 BN -> pool atomics ----------------
__global__ void k_bn_pool(const float4* __restrict__ Z, const float* __restrict__ stats,
                          const float* __restrict__ gamma, const float* __restrict__ beta,
                          const int* __restrict__ batch, float4* __restrict__ pool) {
    __shared__ float sc[64], sh[64];
    int t = threadIdx.x;
    if (t < 64) {
        float mean = stats[t] * (1.0f / NN);
        float var  = stats[64 + t] * (1.0f / NN) - mean * mean;
        float s = gamma[t] * rsqrtf(var + BN_EPS);
        sc[t] = s;
        sh[t] = beta[t] - mean * s;
    }
    __syncthreads();
    int i = blockIdx.x * blockDim.x + t;
    if (i >= NN * 16) return;
    int c = (i & 15) * 4;
    float4 z = Z[i];
    float4 v = make_float4(z.x * sc[c + 0] + sh[c + 0],
                           z.y * sc[c + 1] + sh[c + 1],
                           z.z * sc[c + 2] + sh[c + 2],
                           z.w * sc[c + 3] + sh[c + 3]);
    atomicAdd(&pool[batch[i >> 4] * 16 + (i & 15)], v);
}

// tiny tail GEMMs
template <int K, int M, bool RELU>
__global__ void k_smallgemm(const float* __restrict__ A, const float* __restrict__ W,
                            const float* __restrict__ b, float* __restrict__ C, int rows) {
    int idx = blockIdx.x * blockDim.x + threadIdx.x;
    if (idx >= rows * M) return;
    int r = idx / M, c = idx % M;
    float acc = b[c];
#pragma unroll 8
    for (int k = 0; k < K; k++) acc += A[r * K + k] * W[k * M + c];
    C[idx] = RELU ? fmaxf(acc, 0.0f) : acc;
}

// ---------------- launch ----------------

extern "C" void kernel_launch(void* const* d_in, const int* in_sizes, int n_in,
                              void* d_out, int out_size) {
    const float* x     = (const float*)d_in[0];
    const int*   ei    = (const int*)d_in[1];
    const int*   batch = (const int*)d_in[2];
    const float* prm[22];
    for (int i = 0; i < 22; i++) prm[i] = (const float*)d_in[3 + i];
    // per layer L at 6L: w_a,b_a,w_b,b_b,gamma,beta ; 18..21: w_lin0,b_lin0,w_fc1,b_fc1

    float *agg, *z2, *stats, *pool, *mid;
    int *deg, *rowptr, *cursor, *csr;
    cudaGetSymbolAddress((void**)&agg,    g_agg);
    cudaGetSymbolAddress((void**)&z2,     g_z2);
    cudaGetSymbolAddress((void**)&stats,  g_stats);
    cudaGetSymbolAddress((void**)&pool,   g_pool);
    cudaGetSymbolAddress((void**)&mid,    g_mid);
    cudaGetSymbolAddress((void**)&deg,    g_deg);
    cudaGetSymbolAddress((void**)&rowptr, g_rowptr);
    cudaGetSymbolAddress((void**)&cursor, g_cursor);
    cudaGetSymbolAddress((void**)&csr,    g_csr);

    const int MLP_BLOCKS = (NN + 127) / 128;
    const int EDG_BLOCKS = (NE + 255) / 256;
    const int NOD_BLOCKS = (NN * 16 + 255) / 256;

    // -------- CSR build (graph shared by all 3 layers) --------
    k_init<<<(NN + 255) / 256, 256>>>(deg, stats, pool);
    k_hist<<<EDG_BLOCKS, 256>>>(ei, deg);
    k_scan<<<1, 1024>>>(deg, rowptr, cursor);
    k_fill<<<EDG_BLOCKS, 256>>>(ei, cursor, csr);

    // -------- layer 1 (raw x, no BN in gather) --------
    k_gather_bn<<<NOD_BLOCKS, 256>>>((const float4*)x, rowptr, csr,
                                     nullptr, nullptr, nullptr, (float4*)agg);
    k_gin_mlp<<<MLP_BLOCKS, 256>>>(agg, prm[0], prm[1], prm[2], prm[3], z2, stats, NN);

    // -------- layer 2 (gather applies BN1 algebraically) --------
    k_gather_bn<<<NOD_BLOCKS, 256>>>((const float4*)z2, rowptr, csr,
                                     stats, prm[4], prm[5], (float4*)agg);
    k_gin_mlp<<<MLP_BLOCKS, 256>>>(agg, prm[6], prm[7], prm[8], prm[9], z2, stats + 128, NN);

    // -------- layer 3 (gather applies BN2) --------
    k_gather_bn<<<NOD_BLOCKS, 256>>>((const float4*)z2, rowptr, csr,
                                     stats + 128, prm[10], prm[11], (float4*)agg);
    k_gin_mlp<<<MLP_BLOCKS, 256>>>(agg, prm[12], prm[13], prm[14], prm[15], z2, stats + 256, NN);

    // -------- BN3 -> pool, head --------
    k_bn_pool<<<NOD_BLOCKS, 256>>>((const float4*)z2, stats + 256, prm[16], prm[17],
                                   batch, (float4*)pool);
    k_smallgemm<64, 128, false><<<(NGR * 128 + 255) / 256, 256>>>((float*)pool, prm[18], prm[19], mid, NGR);
    k_smallgemm<128, 64, true><<<(NGR * 64 + 255) / 256, 256>>>(mid, prm[20], prm[21], (float*)d_out, NGR);
}